// round 1
// baseline (speedup 1.0000x reference)
#include <cuda_runtime.h>
#include <math.h>
#include <stdint.h>

#define Bsz  64
#define Tlen 2048
#define Hd   128
#define G4   512   // 4*H gates
#define Cout 7

// ---------------- device scratch (no allocations allowed) ----------------
__device__ float g_v0[G4];                         // W_ih0 @ ff_w
__device__ float g_u0[G4];                         // W_ih0 @ ff_b + b0
__device__ float g_H1[(size_t)Tlen * Bsz * Hd];    // layer-0 hidden outputs [t][b][h]  (64 MB)
__device__ float g_G1[(size_t)Tlen * Bsz * G4];    // layer-1 input-gate preacts [t][b][g] (256 MB)
__device__ float g_pool[Bsz * 3 * Hd];             // [b][mean|max|last]

__device__ __forceinline__ float sigf(float x) { return 1.0f / (1.0f + __expf(-x)); }

// ---------------- prep: fold input projection into per-gate scalar affine ----------------
__global__ void prep_kernel(const float* __restrict__ Wih0, const float* __restrict__ ffw,
                            const float* __restrict__ ffb,  const float* __restrict__ b0) {
    int g = threadIdx.x;  // 512 threads
    float v = 0.f, u = 0.f;
    #pragma unroll 4
    for (int k = 0; k < Hd; k++) {
        float w = Wih0[g * Hd + k];
        v = fmaf(w, ffw[k], v);
        u = fmaf(w, ffb[k], u);
    }
    g_v0[g] = v;
    g_u0[g] = u + b0[g];
}

// ---------------- recurrent LSTM layer: 1 batch element per CTA ----------------
// Thread t owns gate g=t (512 gates). Weights: k in [0,64) in registers,
// k in [64,128) in smem (k-major float4 tiles, conflict-free coalesced LDS.128).
// h broadcast from smem (broadcast = 1 wavefront per LDS.128).
template <int LAYER>
__global__ __launch_bounds__(512, 1)
void lstm_kernel(const float* __restrict__ Whh,
                 const float* __restrict__ xin,       // layer0: x [B][T]
                 const int*   __restrict__ lengths) { // layer1: pooling
    extern __shared__ float sm[];
    float4* Wsm4  = (float4*)sm;              // 16*512 float4 = 128 KB
    float*  h_s   = sm + 16 * 512 * 4;        // 128 floats
    float*  act_s = h_s + Hd;                 // 512 floats
    float*  xrow  = act_s + G4;               // 2048 floats (layer0 only)

    const int g = threadIdx.x;
    const int b = blockIdx.x;

    // ---- stage weights ----
    float4 wreg[16];
    #pragma unroll
    for (int j = 0; j < 16; j++)
        wreg[j] = *(const float4*)(Whh + (size_t)g * Hd + 4 * j);
    #pragma unroll
    for (int j = 0; j < 16; j++)
        Wsm4[j * 512 + g] = *(const float4*)(Whh + (size_t)g * Hd + 64 + 4 * j);

    float vg = 0.f, ug = 0.f;
    if (LAYER == 0) {
        vg = g_v0[g];
        ug = g_u0[g];
        for (int i = g; i < Tlen; i += 512) xrow[i] = xin[(size_t)b * Tlen + i];
    }
    if (g < Hd) h_s[g] = 0.f;

    float cst = 0.f;                       // cell state (threads 0..127)
    float sum = 0.f, mx = -INFINITY, last = 0.f;
    const int len = lengths[b];

    float g1n = 0.f;
    if (LAYER == 1) g1n = g_G1[(size_t)b * G4 + g];   // prefetch t=0
    __syncthreads();

    const float4* h4 = (const float4*)h_s;

    for (int t = 0; t < Tlen; t++) {
        float acc0, acc1 = 0.f;
        if (LAYER == 0) {
            acc0 = fmaf(xrow[t], vg, ug);
        } else {
            acc0 = g1n;
            if (t + 1 < Tlen)  // software prefetch next step's input gates
                g1n = g_G1[((size_t)(t + 1) * Bsz + b) * G4 + g];
        }
        // k in [0,64): register weights, h from smem (broadcast)
        #pragma unroll
        for (int j = 0; j < 16; j++) {
            float4 hv = h4[j];
            float4 wv = wreg[j];
            acc0 = fmaf(hv.x, wv.x, acc0);
            acc1 = fmaf(hv.y, wv.y, acc1);
            acc0 = fmaf(hv.z, wv.z, acc0);
            acc1 = fmaf(hv.w, wv.w, acc1);
        }
        // k in [64,128): smem weights (coalesced) + h broadcast
        #pragma unroll
        for (int j = 0; j < 16; j++) {
            float4 hv = h4[16 + j];
            float4 wv = Wsm4[j * 512 + g];
            acc0 = fmaf(hv.x, wv.x, acc0);
            acc1 = fmaf(hv.y, wv.y, acc1);
            acc0 = fmaf(hv.z, wv.z, acc0);
            acc1 = fmaf(hv.w, wv.w, acc1);
        }
        float a = acc0 + acc1;

        // gate nonlinearity (warp-uniform branches: boundaries at multiples of 128)
        float act;
        if (g < 256)       act = sigf(a);    // i, f
        else if (g < 384)  act = tanhf(a);   // g
        else               act = sigf(a);    // o
        act_s[g] = act;
        __syncthreads();

        if (g < Hd) {
            float iv = act_s[g], fv = act_s[Hd + g];
            float gv = act_s[2 * Hd + g], ov = act_s[3 * Hd + g];
            cst = fmaf(fv, cst, iv * gv);
            float h = ov * tanhf(cst);
            h_s[g] = h;
            if (LAYER == 0) {
                g_H1[((size_t)t * Bsz + b) * Hd + g] = h;
            } else {
                if (t < len) { sum += h; mx = fmaxf(mx, h); }
                if (t == len - 1) last = h;
            }
        }
        __syncthreads();
    }

    if (LAYER == 1 && g < Hd) {
        g_pool[b * 384 + g]           = sum / (float)len;
        g_pool[b * 384 + Hd + g]      = mx;
        g_pool[b * 384 + 2 * Hd + g]  = last;
    }
}

// ---------------- GEMM: G1[t*B+b][n] = sum_k H1[t*B+b][k] * Wih1[n][k] + b1[n] ----------------
// M = 131072, N = 512, K = 128. Register-tiled 128x128 blocks, 256 threads, 8x8 per thread.
__global__ __launch_bounds__(256)
void gemm_g1_kernel(const float* __restrict__ Wih1, const float* __restrict__ b1) {
    __shared__ float As[16][128];
    __shared__ float Bs[16][128];
    const int m0 = blockIdx.x * 128;
    const int n0 = blockIdx.y * 128;
    const int tid = threadIdx.x;
    const int tr = (tid >> 4) * 8;   // 0..120
    const int tc = (tid & 15) * 8;

    float acc[8][8];
    #pragma unroll
    for (int i = 0; i < 8; i++)
        #pragma unroll
        for (int j = 0; j < 8; j++) acc[i][j] = 0.f;

    for (int k0 = 0; k0 < 128; k0 += 16) {
        for (int l = tid; l < 512; l += 256) {
            int row = l >> 2, c4 = (l & 3) * 4;
            float4 v = *(const float4*)(g_H1 + (size_t)(m0 + row) * 128 + k0 + c4);
            As[c4 + 0][row] = v.x; As[c4 + 1][row] = v.y;
            As[c4 + 2][row] = v.z; As[c4 + 3][row] = v.w;
        }
        for (int l = tid; l < 512; l += 256) {
            int row = l >> 2, c4 = (l & 3) * 4;
            float4 v = *(const float4*)(Wih1 + (size_t)(n0 + row) * 128 + k0 + c4);
            Bs[c4 + 0][row] = v.x; Bs[c4 + 1][row] = v.y;
            Bs[c4 + 2][row] = v.z; Bs[c4 + 3][row] = v.w;
        }
        __syncthreads();
        #pragma unroll
        for (int kk = 0; kk < 16; kk++) {
            float4 a0 = *(const float4*)&As[kk][tr];
            float4 a1 = *(const float4*)&As[kk][tr + 4];
            float4 b0v = *(const float4*)&Bs[kk][tc];
            float4 b1v = *(const float4*)&Bs[kk][tc + 4];
            float ra[8] = {a0.x, a0.y, a0.z, a0.w, a1.x, a1.y, a1.z, a1.w};
            float rb[8] = {b0v.x, b0v.y, b0v.z, b0v.w, b1v.x, b1v.y, b1v.z, b1v.w};
            #pragma unroll
            for (int i = 0; i < 8; i++)
                #pragma unroll
                for (int j = 0; j < 8; j++)
                    acc[i][j] = fmaf(ra[i], rb[j], acc[i][j]);
        }
        __syncthreads();
    }
    #pragma unroll
    for (int i = 0; i < 8; i++) {
        #pragma unroll
        for (int j = 0; j < 8; j += 4) {
            float4 v;
            v.x = acc[i][j + 0] + b1[n0 + tc + j + 0];
            v.y = acc[i][j + 1] + b1[n0 + tc + j + 1];
            v.z = acc[i][j + 2] + b1[n0 + tc + j + 2];
            v.w = acc[i][j + 3] + b1[n0 + tc + j + 3];
            *(float4*)(g_G1 + (size_t)(m0 + tr + i) * G4 + n0 + tc + j) = v;
        }
    }
}

// ---------------- final linear: out[b][c] = pool[b] . lin_w[c] + lin_b[c] ----------------
__global__ void final_kernel(const float* __restrict__ lw, const float* __restrict__ lb,
                             float* __restrict__ out) {
    int tid = blockIdx.x * blockDim.x + threadIdx.x;
    if (tid >= Bsz * Cout) return;
    int b = tid / Cout, c = tid % Cout;
    float s = lb[c];
    const float* p = g_pool + b * 384;
    const float* w = lw + c * 384;
    #pragma unroll 8
    for (int j = 0; j < 384; j++) s = fmaf(p[j], w[j], s);
    out[tid] = s;
}

// ---------------- launch ----------------
extern "C" void kernel_launch(void* const* d_in, const int* in_sizes, int n_in,
                              void* d_out, int out_size) {
    const float* x    = (const float*)d_in[0];
    const int*   lens = (const int*)  d_in[1];
    const float* ffw  = (const float*)d_in[2];
    const float* ffb  = (const float*)d_in[3];
    const float* Wih0 = (const float*)d_in[4];
    const float* Whh0 = (const float*)d_in[5];
    const float* b0   = (const float*)d_in[6];
    const float* Wih1 = (const float*)d_in[7];
    const float* Whh1 = (const float*)d_in[8];
    const float* b1   = (const float*)d_in[9];
    const float* lw   = (const float*)d_in[10];
    const float* lb   = (const float*)d_in[11];
    float* out = (float*)d_out;

    const int SMEM = (16 * 512 * 4 + Hd + G4 + Tlen) * (int)sizeof(float);  // 141824 B
    cudaFuncSetAttribute(lstm_kernel<0>, cudaFuncAttributeMaxDynamicSharedMemorySize, SMEM);
    cudaFuncSetAttribute(lstm_kernel<1>, cudaFuncAttributeMaxDynamicSharedMemorySize, SMEM);

    prep_kernel<<<1, 512>>>(Wih0, ffw, ffb, b0);
    lstm_kernel<0><<<Bsz, 512, SMEM>>>(Whh0, x, lens);
    dim3 ggrid((Tlen * Bsz) / 128, G4 / 128);
    gemm_g1_kernel<<<ggrid, 256>>>(Wih1, b1);
    lstm_kernel<1><<<Bsz, 512, SMEM>>>(Whh1, x, lens);
    final_kernel<<<1, 512>>>(lw, lb, out);
}

// round 2
// speedup vs baseline: 1.3587x; 1.3587x over previous
#include <cuda_runtime.h>
#include <math.h>
#include <stdint.h>

#define Bsz  64
#define Tlen 2048
#define Hd   128
#define G4   512   // 4*H gates
#define Cout 7

// weight split per gate: k in [0, 4*REGJ) in registers, rest in smem
#define REGJ 22                 // 22 float4 = 88 floats in registers per gate
#define SMJ  10                 // 10 float4 = 40 floats in smem per gate
#define KSPLIT (4 * REGJ)       // 88

// ---------------- device scratch (no allocations allowed) ----------------
__device__ float g_v0[G4];                         // W_ih0 @ ff_w
__device__ float g_u0[G4];                         // W_ih0 @ ff_b + b0
__device__ float g_H1[(size_t)Tlen * Bsz * Hd];    // layer-0 hidden outputs [t][b][h]
__device__ float g_G1[(size_t)Tlen * Bsz * G4];    // layer-1 input-gate preacts [t][b][g]
__device__ float g_pool[Bsz * 3 * Hd];             // [b][mean|max|last]

__device__ __forceinline__ float sigf(float x) { return 1.0f / (1.0f + __expf(-x)); }

// ---------------- prep: fold input projection into per-gate scalar affine ----------------
__global__ void prep_kernel(const float* __restrict__ Wih0, const float* __restrict__ ffw,
                            const float* __restrict__ ffb,  const float* __restrict__ b0) {
    int g = threadIdx.x;  // 512 threads
    float v = 0.f, u = 0.f;
    #pragma unroll 4
    for (int k = 0; k < Hd; k++) {
        float w = Wih0[g * Hd + k];
        v = fmaf(w, ffw[k], v);
        u = fmaf(w, ffb[k], u);
    }
    g_v0[g] = v;
    g_u0[g] = u + b0[g];
}

// ---------------- recurrent LSTM layer: 1 batch element per CTA ----------------
// 256 threads; thread owns gates g0=tid and g1=tid+256.
// 88/128 weight cols per gate in registers, 40/128 in smem (coalesced float4).
// h broadcast from smem, read ONCE per thread, reused for both gates.
template <int LAYER>
__global__ __launch_bounds__(256, 1)
void lstm_kernel(const float* __restrict__ Whh,
                 const float* __restrict__ xin,       // layer0: x [B][T]
                 const int*   __restrict__ lengths) { // layer1: pooling
    extern __shared__ float sm[];
    float4* Wsm4  = (float4*)sm;               // SMJ*512 float4 = 80 KB
    float*  h_s   = sm + SMJ * 512 * 4;        // 128 floats
    float*  act_s = h_s + Hd;                  // 512 floats
    float*  xrow  = act_s + G4;                // 2048 floats (layer0 only)

    const int tid = threadIdx.x;
    const int g0  = tid;
    const int g1  = tid + 256;
    const int b   = blockIdx.x;

    // ---- stage weights ----
    float4 w0[REGJ], w1[REGJ];
    #pragma unroll
    for (int j = 0; j < REGJ; j++) {
        w0[j] = *(const float4*)(Whh + (size_t)g0 * Hd + 4 * j);
        w1[j] = *(const float4*)(Whh + (size_t)g1 * Hd + 4 * j);
    }
    #pragma unroll
    for (int kk = 0; kk < SMJ; kk++) {
        Wsm4[kk * 512 + g0] = *(const float4*)(Whh + (size_t)g0 * Hd + KSPLIT + 4 * kk);
        Wsm4[kk * 512 + g1] = *(const float4*)(Whh + (size_t)g1 * Hd + KSPLIT + 4 * kk);
    }

    float vg0 = 0.f, ug0 = 0.f, vg1 = 0.f, ug1 = 0.f;
    if (LAYER == 0) {
        vg0 = g_v0[g0]; ug0 = g_u0[g0];
        vg1 = g_v0[g1]; ug1 = g_u0[g1];
        for (int i = tid; i < Tlen; i += 256) xrow[i] = xin[(size_t)b * Tlen + i];
    }
    if (tid < Hd) h_s[tid] = 0.f;

    float cst = 0.f;                       // cell state (threads 0..127)
    float sum = 0.f, mx = -INFINITY, last = 0.f;
    const int len = lengths[b];

    float g1n0 = 0.f, g1n1 = 0.f;
    if (LAYER == 1) {                      // prefetch t=0
        g1n0 = g_G1[(size_t)b * G4 + g0];
        g1n1 = g_G1[(size_t)b * G4 + g1];
    }
    __syncthreads();

    const float4* h4 = (const float4*)h_s;

    for (int t = 0; t < Tlen; t++) {
        float a00, a01 = 0.f, a10, a11 = 0.f;
        if (LAYER == 0) {
            float xv = xrow[t];
            a00 = fmaf(xv, vg0, ug0);
            a10 = fmaf(xv, vg1, ug1);
        } else {
            a00 = g1n0;
            a10 = g1n1;
            if (t + 1 < Tlen) {            // software prefetch next step's input gates
                size_t base = ((size_t)(t + 1) * Bsz + b) * G4;
                g1n0 = g_G1[base + g0];
                g1n1 = g_G1[base + g1];
            }
        }
        // k in [0, KSPLIT): register weights, h from smem (broadcast, read once)
        #pragma unroll
        for (int j = 0; j < REGJ; j++) {
            float4 hv = h4[j];
            float4 a = w0[j], c = w1[j];
            a00 = fmaf(hv.x, a.x, a00);
            a01 = fmaf(hv.y, a.y, a01);
            a00 = fmaf(hv.z, a.z, a00);
            a01 = fmaf(hv.w, a.w, a01);
            a10 = fmaf(hv.x, c.x, a10);
            a11 = fmaf(hv.y, c.y, a11);
            a10 = fmaf(hv.z, c.z, a10);
            a11 = fmaf(hv.w, c.w, a11);
        }
        // k in [KSPLIT, 128): smem weights (coalesced) + h broadcast
        #pragma unroll
        for (int kk = 0; kk < SMJ; kk++) {
            float4 hv = h4[REGJ + kk];
            float4 a = Wsm4[kk * 512 + g0];
            float4 c = Wsm4[kk * 512 + g1];
            a00 = fmaf(hv.x, a.x, a00);
            a01 = fmaf(hv.y, a.y, a01);
            a00 = fmaf(hv.z, a.z, a00);
            a01 = fmaf(hv.w, a.w, a01);
            a10 = fmaf(hv.x, c.x, a10);
            a11 = fmaf(hv.y, c.y, a11);
            a10 = fmaf(hv.z, c.z, a10);
            a11 = fmaf(hv.w, c.w, a11);
        }
        float A0 = a00 + a01;              // gate g0 in [0,256): i or f -> sigmoid
        float A1 = a10 + a11;              // gate g1 in [256,512): g (tanh) or o (sigmoid)

        act_s[g0] = sigf(A0);
        act_s[g1] = (tid < 128) ? tanhf(A1) : sigf(A1);   // warp-uniform branch
        __syncthreads();

        if (tid < Hd) {
            float iv = act_s[tid],          fv = act_s[Hd + tid];
            float gv = act_s[2 * Hd + tid], ov = act_s[3 * Hd + tid];
            cst = fmaf(fv, cst, iv * gv);
            float h = ov * tanhf(cst);
            h_s[tid] = h;
            if (LAYER == 0) {
                g_H1[((size_t)t * Bsz + b) * Hd + tid] = h;
            } else {
                if (t < len) { sum += h; mx = fmaxf(mx, h); }
                if (t == len - 1) last = h;
            }
        }
        __syncthreads();
    }

    if (LAYER == 1 && tid < Hd) {
        g_pool[b * 384 + tid]           = sum / (float)len;
        g_pool[b * 384 + Hd + tid]      = mx;
        g_pool[b * 384 + 2 * Hd + tid]  = last;
    }
}

// ---------------- GEMM: G1[t*B+b][n] = sum_k H1[t*B+b][k] * Wih1[n][k] + b1[n] ----------------
// M = 131072, N = 512, K = 128. Register-tiled 128x128 blocks, 256 threads, 8x8 per thread.
__global__ __launch_bounds__(256)
void gemm_g1_kernel(const float* __restrict__ Wih1, const float* __restrict__ b1) {
    __shared__ float As[16][128];
    __shared__ float Bs[16][128];
    const int m0 = blockIdx.x * 128;
    const int n0 = blockIdx.y * 128;
    const int tid = threadIdx.x;
    const int tr = (tid >> 4) * 8;
    const int tc = (tid & 15) * 8;

    float acc[8][8];
    #pragma unroll
    for (int i = 0; i < 8; i++)
        #pragma unroll
        for (int j = 0; j < 8; j++) acc[i][j] = 0.f;

    for (int k0 = 0; k0 < 128; k0 += 16) {
        for (int l = tid; l < 512; l += 256) {
            int row = l >> 2, c4 = (l & 3) * 4;
            float4 v = *(const float4*)(g_H1 + (size_t)(m0 + row) * 128 + k0 + c4);
            As[c4 + 0][row] = v.x; As[c4 + 1][row] = v.y;
            As[c4 + 2][row] = v.z; As[c4 + 3][row] = v.w;
        }
        for (int l = tid; l < 512; l += 256) {
            int row = l >> 2, c4 = (l & 3) * 4;
            float4 v = *(const float4*)(Wih1 + (size_t)(n0 + row) * 128 + k0 + c4);
            Bs[c4 + 0][row] = v.x; Bs[c4 + 1][row] = v.y;
            Bs[c4 + 2][row] = v.z; Bs[c4 + 3][row] = v.w;
        }
        __syncthreads();
        #pragma unroll
        for (int kk = 0; kk < 16; kk++) {
            float4 a0 = *(const float4*)&As[kk][tr];
            float4 a1 = *(const float4*)&As[kk][tr + 4];
            float4 b0v = *(const float4*)&Bs[kk][tc];
            float4 b1v = *(const float4*)&Bs[kk][tc + 4];
            float ra[8] = {a0.x, a0.y, a0.z, a0.w, a1.x, a1.y, a1.z, a1.w};
            float rb[8] = {b0v.x, b0v.y, b0v.z, b0v.w, b1v.x, b1v.y, b1v.z, b1v.w};
            #pragma unroll
            for (int i = 0; i < 8; i++)
                #pragma unroll
                for (int j = 0; j < 8; j++)
                    acc[i][j] = fmaf(ra[i], rb[j], acc[i][j]);
        }
        __syncthreads();
    }
    #pragma unroll
    for (int i = 0; i < 8; i++) {
        #pragma unroll
        for (int j = 0; j < 8; j += 4) {
            float4 v;
            v.x = acc[i][j + 0] + b1[n0 + tc + j + 0];
            v.y = acc[i][j + 1] + b1[n0 + tc + j + 1];
            v.z = acc[i][j + 2] + b1[n0 + tc + j + 2];
            v.w = acc[i][j + 3] + b1[n0 + tc + j + 3];
            *(float4*)(g_G1 + (size_t)(m0 + tr + i) * G4 + n0 + tc + j) = v;
        }
    }
}

// ---------------- final linear ----------------
__global__ void final_kernel(const float* __restrict__ lw, const float* __restrict__ lb,
                             float* __restrict__ out) {
    int tid = blockIdx.x * blockDim.x + threadIdx.x;
    if (tid >= Bsz * Cout) return;
    int b = tid / Cout, c = tid % Cout;
    float s = lb[c];
    const float* p = g_pool + b * 384;
    const float* w = lw + c * 384;
    #pragma unroll 8
    for (int j = 0; j < 384; j++) s = fmaf(p[j], w[j], s);
    out[tid] = s;
}

// ---------------- launch ----------------
extern "C" void kernel_launch(void* const* d_in, const int* in_sizes, int n_in,
                              void* d_out, int out_size) {
    const float* x    = (const float*)d_in[0];
    const int*   lens = (const int*)  d_in[1];
    const float* ffw  = (const float*)d_in[2];
    const float* ffb  = (const float*)d_in[3];
    const float* Wih0 = (const float*)d_in[4];
    const float* Whh0 = (const float*)d_in[5];
    const float* b0   = (const float*)d_in[6];
    const float* Wih1 = (const float*)d_in[7];
    const float* Whh1 = (const float*)d_in[8];
    const float* b1   = (const float*)d_in[9];
    const float* lw   = (const float*)d_in[10];
    const float* lb   = (const float*)d_in[11];
    float* out = (float*)d_out;

    const int SMEM = (SMJ * 512 * 4 + Hd + G4 + Tlen) * (int)sizeof(float);  // ~92.7 KB
    cudaFuncSetAttribute(lstm_kernel<0>, cudaFuncAttributeMaxDynamicSharedMemorySize, SMEM);
    cudaFuncSetAttribute(lstm_kernel<1>, cudaFuncAttributeMaxDynamicSharedMemorySize, SMEM);

    prep_kernel<<<1, 512>>>(Wih0, ffw, ffb, b0);
    lstm_kernel<0><<<Bsz, 256, SMEM>>>(Whh0, x, lens);
    dim3 ggrid((Tlen * Bsz) / 128, G4 / 128);
    gemm_g1_kernel<<<ggrid, 256>>>(Wih1, b1);
    lstm_kernel<1><<<Bsz, 256, SMEM>>>(Whh1, x, lens);
    final_kernel<<<1, 512>>>(lw, lb, out);
}